// round 1
// baseline (speedup 1.0000x reference)
#include <cuda_runtime.h>
#include <math.h>

#define B_     16
#define T_     2048
#define C_     512
#define G_     2
#define D_     256
#define V_     320
#define N_TOK  (B_*T_)           // 32768
#define NPAIR  (N_TOK*G_)        // 65536
#define GN_N   ((double)(T_*D_)) // 524288 elems per (b,g)

// ---------------- scratch (device globals; no runtime allocation) ------------
__device__ float  g_y  [N_TOK*C_];   // 64 MB: conv output
__device__ float  g_ze [N_TOK*C_];   // 64 MB: normalized
__device__ float  g_zsq[NPAIR];
__device__ unsigned long long g_best[NPAIR];
__device__ double g_p1s[32][32];     // GEMM1 block partial sums  [b*2+g][bt*2+bn]
__device__ double g_p1q[32][32];     // GEMM1 block partial sumsq
__device__ float  g_mu  [B_*G_];
__device__ float  g_rstd[B_*G_];
__device__ float  g_esq [G_*V_];
__device__ int    g_hist[G_*V_];
__device__ double g_lpart[8192];     // per-block loss partials

__device__ __forceinline__ void ld8(const float* __restrict__ p, float* r) {
    float4 a = *(const float4*)p;
    float4 b = *(const float4*)(p + 4);
    r[0]=a.x; r[1]=a.y; r[2]=a.z; r[3]=a.w;
    r[4]=b.x; r[5]=b.y; r[6]=b.z; r[7]=b.w;
}

// ---------------- K0: init (g_best, hist, e_sq) ------------------------------
__global__ void k_init(const float* __restrict__ emb) {
    int gt = blockIdx.x * blockDim.x + threadIdx.x;
    if (gt < NPAIR) g_best[gt] = 0xFFFFFFFFFFFFFFFFULL;
    if (gt < G_*V_) g_hist[gt] = 0;
    int i = gt - NPAIR;
    if (i >= 0 && i < G_*V_) {
        int g = i / V_, v = i % V_;
        const float4* p = (const float4*)(emb + (size_t)v * C_ + g * D_);
        float s = 0.f;
        #pragma unroll 16
        for (int q = 0; q < D_/4; q++) {
            float4 e = p[q];
            s += e.x*e.x + e.y*e.y + e.z*e.z + e.w*e.w;
        }
        g_esq[i] = s;
    }
}

// ---------------- K1: grouped GEMM  y[b,t,g,o] = sum_i x * w[g,o,i] ----------
// per block: 128 (t) x 128 (o), K=256 in chunks of 16. 256 thr, 8x8 microtile.
__global__ __launch_bounds__(256) void k_gemm1(const float* __restrict__ x,
                                               const float* __restrict__ w) {
    __shared__ float As[16][132];
    __shared__ float Bs[16][132];
    __shared__ double rs[256], rq[256];

    const int bt  = blockIdx.x;        // 0..15 t-tiles
    const int bn  = blockIdx.y;        // 0..1  o-tiles
    const int bz  = blockIdx.z;        // b*2+g
    const int b   = bz >> 1, g = bz & 1;
    const int tid = threadIdx.x;
    const int tx  = tid & 15, ty = tid >> 4;

    const float* Ab = x + ((size_t)(b*T_ + bt*128)) * C_ + g * D_;
    const float* Bb = w + (size_t)g * D_ * D_ + (size_t)(bn*128) * D_;

    const int lk = (tid & 3) * 4;  // k quad
    const int lm = tid >> 2;       // 0..63

    float acc[8][8];
    #pragma unroll
    for (int i = 0; i < 8; i++)
        #pragma unroll
        for (int j = 0; j < 8; j++) acc[i][j] = 0.f;

    for (int kc = 0; kc < D_; kc += 16) {
        #pragma unroll
        for (int r = 0; r < 2; r++) {
            int m = lm + r*64;
            float4 va = *(const float4*)(Ab + (size_t)m*C_ + kc + lk);
            As[lk+0][m]=va.x; As[lk+1][m]=va.y; As[lk+2][m]=va.z; As[lk+3][m]=va.w;
            float4 vb = *(const float4*)(Bb + (size_t)m*D_ + kc + lk);
            Bs[lk+0][m]=vb.x; Bs[lk+1][m]=vb.y; Bs[lk+2][m]=vb.z; Bs[lk+3][m]=vb.w;
        }
        __syncthreads();
        #pragma unroll
        for (int kk = 0; kk < 16; kk++) {
            float a[8], bf[8];
            *(float4*)(a)    = *(const float4*)&As[kk][ty*4];
            *(float4*)(a+4)  = *(const float4*)&As[kk][64 + ty*4];
            *(float4*)(bf)   = *(const float4*)&Bs[kk][tx*4];
            *(float4*)(bf+4) = *(const float4*)&Bs[kk][64 + tx*4];
            #pragma unroll
            for (int i = 0; i < 8; i++)
                #pragma unroll
                for (int j = 0; j < 8; j++)
                    acc[i][j] = fmaf(a[i], bf[j], acc[i][j]);
        }
        __syncthreads();
    }

    // store y + accumulate stats
    double s = 0.0, q = 0.0;
    float* Cb = g_y + ((size_t)(b*T_ + bt*128)) * C_ + g * D_ + bn*128;
    #pragma unroll
    for (int i = 0; i < 8; i++) {
        int m = (i < 4) ? (ty*4 + i) : (64 + ty*4 + (i-4));
        #pragma unroll
        for (int j = 0; j < 8; j++) { double v = acc[i][j]; s += v; q += v*v; }
        *(float4*)(Cb + (size_t)m*C_ + tx*4)
            = make_float4(acc[i][0], acc[i][1], acc[i][2], acc[i][3]);
        *(float4*)(Cb + (size_t)m*C_ + 64 + tx*4)
            = make_float4(acc[i][4], acc[i][5], acc[i][6], acc[i][7]);
    }
    rs[tid] = s; rq[tid] = q;
    __syncthreads();
    for (int off = 128; off > 0; off >>= 1) {
        if (tid < off) { rs[tid] += rs[tid+off]; rq[tid] += rq[tid+off]; }
        __syncthreads();
    }
    if (tid == 0) {
        g_p1s[bz][bt*2 + bn] = rs[0];
        g_p1q[bz][bt*2 + bn] = rq[0];
    }
}

// ---------------- K2: finalize groupnorm stats (deterministic order) ---------
__global__ void k_stats() {
    int i = threadIdx.x;  // 0..31 = b*2+g
    if (i >= B_*G_) return;
    double s = 0.0, q = 0.0;
    for (int j = 0; j < 32; j++) { s += g_p1s[i][j]; q += g_p1q[i][j]; }
    double mu  = s / GN_N;
    double var = q / GN_N - mu * mu;
    g_mu[i]   = (float)mu;
    g_rstd[i] = (float)(1.0 / sqrt(var + 1e-5));
}

// ---------------- K3: normalize + affine -> ze, z_sq -------------------------
// one warp per (token, g). grid = 8192 blocks x 256 (exact)
__global__ __launch_bounds__(256) void k_norm(const float* __restrict__ gn_w,
                                              const float* __restrict__ gn_b) {
    int wg   = (blockIdx.x * 256 + threadIdx.x) >> 5;  // 0..65535
    int lane = threadIdx.x & 31;
    int n = wg >> 1, g = wg & 1;
    int b = n >> 11;
    float mu = g_mu[b*G_ + g], rstd = g_rstd[b*G_ + g];
    size_t base = (size_t)n * C_ + g * D_ + lane * 8;
    float y[8], ww[8], bb[8], z[8];
    ld8(g_y + base, y);
    ld8(gn_w + g*D_ + lane*8, ww);
    ld8(gn_b + g*D_ + lane*8, bb);
    float s = 0.f;
    #pragma unroll
    for (int i = 0; i < 8; i++) {
        z[i] = fmaf((y[i] - mu) * rstd, ww[i], bb[i]);
        s = fmaf(z[i], z[i], s);
    }
    *(float4*)(g_ze + base)     = make_float4(z[0], z[1], z[2], z[3]);
    *(float4*)(g_ze + base + 4) = make_float4(z[4], z[5], z[6], z[7]);
    #pragma unroll
    for (int off = 16; off > 0; off >>= 1) s += __shfl_xor_sync(0xffffffffu, s, off);
    if (lane == 0) g_zsq[wg] = s;
}

// ---------------- K4: VQ GEMM (ze @ emb^T) + packed argmin -------------------
// tile: 128 (tokens) x 64 (codes), K=256. 256 thr, 8x4 microtile.
__global__ __launch_bounds__(256) void k_vq(const float* __restrict__ emb) {
    __shared__ float As[16][132];
    __shared__ float Bs[16][68];

    const int bm  = blockIdx.x;       // 0..255 token tiles
    const int bn  = blockIdx.y;       // 0..4   code tiles
    const int g   = blockIdx.z;       // 0..1
    const int tid = threadIdx.x;
    const int tx  = tid & 15, ty = tid >> 4;

    const float* Ab = g_ze + (size_t)(bm*128) * C_ + g * D_;
    const float* Bb = emb  + (size_t)(bn*64)  * C_ + g * D_;

    const int lk  = (tid & 3) * 4;
    const int lm  = tid >> 2;

    float acc[8][4];
    #pragma unroll
    for (int i = 0; i < 8; i++)
        #pragma unroll
        for (int j = 0; j < 4; j++) acc[i][j] = 0.f;

    for (int kc = 0; kc < D_; kc += 16) {
        #pragma unroll
        for (int r = 0; r < 2; r++) {
            int m = lm + r*64;
            float4 va = *(const float4*)(Ab + (size_t)m*C_ + kc + lk);
            As[lk+0][m]=va.x; As[lk+1][m]=va.y; As[lk+2][m]=va.z; As[lk+3][m]=va.w;
        }
        {
            float4 vb = *(const float4*)(Bb + (size_t)lm*C_ + kc + lk);
            Bs[lk+0][lm]=vb.x; Bs[lk+1][lm]=vb.y; Bs[lk+2][lm]=vb.z; Bs[lk+3][lm]=vb.w;
        }
        __syncthreads();
        #pragma unroll
        for (int kk = 0; kk < 16; kk++) {
            float a[8], bf[4];
            *(float4*)(a)   = *(const float4*)&As[kk][ty*4];
            *(float4*)(a+4) = *(const float4*)&As[kk][64 + ty*4];
            *(float4*)(bf)  = *(const float4*)&Bs[kk][tx*4];
            #pragma unroll
            for (int i = 0; i < 8; i++)
                #pragma unroll
                for (int j = 0; j < 4; j++)
                    acc[i][j] = fmaf(a[i], bf[j], acc[i][j]);
        }
        __syncthreads();
    }

    // epilogue: d2 = (z_sq - 2*dot) + e_sq ; packed min
    float eq[4];
    #pragma unroll
    for (int j = 0; j < 4; j++) eq[j] = g_esq[g*V_ + bn*64 + tx*4 + j];

    #pragma unroll
    for (int i = 0; i < 8; i++) {
        int m   = (i < 4) ? (ty*4 + i) : (64 + ty*4 + (i-4));
        int tok = bm*128 + m;
        float zsq = g_zsq[tok*2 + g];
        unsigned long long best = 0xFFFFFFFFFFFFFFFFULL;
        #pragma unroll
        for (int j = 0; j < 4; j++) {
            int v = bn*64 + tx*4 + j;
            float d2 = (zsq - 2.0f * acc[i][j]) + eq[j];
            unsigned long long p =
                ((unsigned long long)__float_as_uint(d2) << 32) | (unsigned)v;
            best = (p < best) ? p : best;
        }
        #pragma unroll
        for (int off = 1; off < 16; off <<= 1) {
            unsigned long long o = __shfl_xor_sync(0xffffffffu, best, off);
            best = (o < best) ? o : best;
        }
        if (tx == 0) atomicMin(&g_best[tok*2 + g], best);
    }
}

// ---------------- K5: gather zq, x_out, loss partials, histogram -------------
// one warp per (token, g). grid = 8192 x 256 (exact).
__global__ __launch_bounds__(256) void k_epi(const float* __restrict__ emb,
                                             float* __restrict__ out) {
    __shared__ float warp_s[8];
    int tid  = threadIdx.x;
    int wg   = (blockIdx.x * 256 + tid) >> 5;
    int lane = tid & 31, wl = tid >> 5;
    int n = wg >> 1, g = wg & 1;
    int v = (int)(unsigned)(g_best[wg] & 0xFFFFFFFFULL);

    size_t zb = (size_t)n * C_ + g * D_ + lane * 8;
    size_t eb = (size_t)v * C_ + g * D_ + lane * 8;
    float ze[8], e[8], r[8];
    ld8(g_ze + zb, ze);
    ld8(emb  + eb, e);
    float s = 0.f;
    #pragma unroll
    for (int i = 0; i < 8; i++) {
        float d = e[i] - ze[i];
        s = fmaf(d, d, s);
        r[i] = (e[i] + ze[i]) - ze[i];  // matches sg(zq)+ze-sg(ze)
    }
    *(float4*)(out + zb)     = make_float4(r[0], r[1], r[2], r[3]);
    *(float4*)(out + zb + 4) = make_float4(r[4], r[5], r[6], r[7]);
    #pragma unroll
    for (int off = 16; off > 0; off >>= 1) s += __shfl_xor_sync(0xffffffffu, s, off);
    if (lane == 0) {
        warp_s[wl] = s;
        atomicAdd(&g_hist[g*V_ + v], 1);
        out[(size_t)N_TOK * C_ + wg] = (float)v;   // idx output (cast to f32)
    }
    __syncthreads();
    if (tid == 0) {
        double a = 0.0;
        #pragma unroll
        for (int i = 0; i < 8; i++) a += (double)warp_s[i];
        g_lpart[blockIdx.x] = a;
    }
}

// ---------------- K6: final scalars (ppl, kmeans_loss), deterministic --------
__global__ void k_final(float* __restrict__ out) {
    __shared__ double sh[512];
    int t = threadIdx.x;  // 512 threads
    double a = 0.0;
    for (int j = t*16; j < t*16 + 16; j++) a += g_lpart[j];  // 8192 = 512*16
    sh[t] = a; __syncthreads();
    for (int off = 256; off > 0; off >>= 1) {
        if (t < off) sh[t] += sh[t+off];
        __syncthreads();
    }
    double S = sh[0];
    __syncthreads();

    double h0 = 0.0, h1 = 0.0;
    if (t < V_) {
        double p0 = (double)g_hist[t]      / (double)N_TOK;
        double p1 = (double)g_hist[V_ + t] / (double)N_TOK;
        h0 = p0 * log(p0 + 1e-7);
        h1 = p1 * log(p1 + 1e-7);
    }
    sh[t] = h0; __syncthreads();
    for (int off = 256; off > 0; off >>= 1) {
        if (t < off) sh[t] += sh[t+off];
        __syncthreads();
    }
    double H0 = sh[0];
    __syncthreads();
    sh[t] = h1; __syncthreads();
    for (int off = 256; off > 0; off >>= 1) {
        if (t < off) sh[t] += sh[t+off];
        __syncthreads();
    }
    double H1 = sh[0];

    if (t == 0) {
        double ppl = exp(-H0) + exp(-H1);
        double l   = S / (double)((size_t)N_TOK * C_);
        out[(size_t)N_TOK * C_ + NPAIR]     = (float)ppl;
        out[(size_t)N_TOK * C_ + NPAIR + 1] = (float)(l + 0.25 * l);
    }
}

// ---------------- launcher ---------------------------------------------------
extern "C" void kernel_launch(void* const* d_in, const int* in_sizes, int n_in,
                              void* d_out, int out_size) {
    const float* x   = (const float*)d_in[0];
    const float* cw  = (const float*)d_in[1];
    const float* gw  = (const float*)d_in[2];
    const float* gb  = (const float*)d_in[3];
    const float* emb = (const float*)d_in[4];
    float* out = (float*)d_out;

    k_init<<<(NPAIR + G_*V_ + 255) / 256, 256>>>(emb);

    dim3 g1(16, 2, 32);
    k_gemm1<<<g1, 256>>>(x, cw);

    k_stats<<<1, 32>>>();

    k_norm<<<8192, 256>>>(gw, gb);

    dim3 g4(256, 5, 2);
    k_vq<<<g4, 256>>>(emb);

    k_epi<<<8192, 256>>>(emb, out);

    k_final<<<1, 512>>>(out);
}